// round 4
// baseline (speedup 1.0000x reference)
#include <cuda_runtime.h>
#include <cstdint>

// Problem constants
#define EXPERTS 16
#define CIN     16
#define COUT    64
#define BATCH   8
#define HDIM    128
#define WDIM    128
#define HW      16384            // 128*128
#define NPIX    131072           // 8*128*128
#define MAXPE   131072           // worst-case entries per expert
#define OUT_ELEMS   8388608      // 8*64*128*128
#define LOGIT_OFF   8388608

// ---------------- scratch (device globals; no allocation) ----------------
__device__ int   g_cnt[EXPERTS];
__device__ int   g_pix[EXPERTS * MAXPE];
__device__ float g_gw [EXPERTS * MAXPE];

// ---------------- f32x2 packed math helpers ----------------
__device__ __forceinline__ unsigned long long pack2(float lo, float hi) {
    unsigned long long r;
    asm("mov.b64 %0, {%1, %2};" : "=l"(r) : "f"(lo), "f"(hi));
    return r;
}
__device__ __forceinline__ void fma2(unsigned long long& d, unsigned long long a, unsigned long long b) {
    // d = a*b + d   (two independent fp32 FMAs, full fp32 rounding)
    asm("fma.rn.f32x2 %0, %1, %2, %0;" : "+l"(d) : "l"(a), "l"(b));
}

// ---------------- kernel 0: reset counters ----------------
__global__ void reset_kernel() {
    if (threadIdx.x < EXPERTS) g_cnt[threadIdx.x] = 0;
}

// ---------------- kernel 1: zero the `out` region (atomic accumulation target) ----
__global__ void zero_out_kernel(float4* __restrict__ out4) {
    int i = blockIdx.x * 256 + threadIdx.x;   // 8192 * 256 = 2,097,152 float4 = 8,388,608 floats
    out4[i] = make_float4(0.f, 0.f, 0.f, 0.f);
}

// ---------------- kernel 2: gate (logits, top-2, list build) ----------------
__global__ void gate_kernel(const float* __restrict__ x,
                            const float* __restrict__ gw,
                            const float* __restrict__ gb,
                            float* __restrict__ out_logits) {
    __shared__ float sgw[256];
    __shared__ float sgb[16];
    __shared__ int   scnt[16];
    __shared__ int   sbase[16];
    int tid = threadIdx.x;
    sgw[tid] = gw[tid];
    if (tid < 16) { sgb[tid] = gb[tid]; scnt[tid] = 0; }
    __syncthreads();

    int p  = blockIdx.x * 256 + tid;          // 512 blocks * 256 = 131072 pixels exactly
    int b  = p >> 14;
    int hw = p & (HW - 1);

    float xv[CIN];
#pragma unroll
    for (int c = 0; c < CIN; c++) xv[c] = x[(b * CIN + c) * HW + hw];

    float best = -1e30f, second = -1e30f;
    int bi = 0, si = 0;
#pragma unroll
    for (int o = 0; o < 16; o++) {
        float l = sgb[o];
#pragma unroll
        for (int c = 0; c < CIN; c++) l = fmaf(sgw[o * 16 + c], xv[c], l);
        out_logits[(b * 16 + o) * HW + hw] = l;
        if (l > best) { second = best; si = bi; best = l; bi = o; }
        else if (l > second) { second = l; si = o; }
    }
    // softmax + top2 renormalization collapses exactly:
    // w0 = p0/(p0+p1) = 1/(1+exp(l1-l0))
    float w0 = 1.0f / (1.0f + expf(second - best));
    float w1 = 1.0f - w0;

    // block-local aggregation of list appends
    int l0 = atomicAdd(&scnt[bi], 1);
    int l1 = atomicAdd(&scnt[si], 1);
    __syncthreads();
    if (tid < 16) sbase[tid] = atomicAdd(&g_cnt[tid], scnt[tid]);
    __syncthreads();

    int q0 = sbase[bi] + l0;
    g_pix[bi * MAXPE + q0] = p;
    g_gw [bi * MAXPE + q0] = w0;
    int q1 = sbase[si] + l1;
    g_pix[si * MAXPE + q1] = p;
    g_gw [si * MAXPE + q1] = w1;
}

// ---------------- kernel 3: expert-major sparse 3x3 conv ----------------
// grid: (512 chunks, 16 experts), 256 threads; each thread = 1 pixel x 64 couts.
__global__ void __launch_bounds__(256, 2)
expert_kernel(const float* __restrict__ x,
              const float* __restrict__ ew,
              const float* __restrict__ eb,
              float* __restrict__ out) {
    __shared__ __align__(16) float wsm[144 * 64];   // [ci*9+k][cout]  36,864 B
    __shared__ float bsm[64];

    int e = blockIdx.y;
    int n = g_cnt[e];
    int base = blockIdx.x << 8;
    if (base >= n) return;

    int tid = threadIdx.x;
    const float* we = ew + e * (COUT * CIN * 9);
    for (int i = tid; i < 144 * 64; i += 256) {
        int cout = i & 63;
        int cik  = i >> 6;                     // ci*9 + k
        wsm[i] = we[cout * 144 + cik];
    }
    if (tid < 64) bsm[tid] = eb[e * 64 + tid];
    __syncthreads();

    int idx = base + tid;
    if (idx >= n) return;

    int   p   = g_pix[e * MAXPE + idx];
    float gwt = g_gw [e * MAXPE + idx];
    int b  = p >> 14;
    int hw = p & (HW - 1);
    int h  = hw >> 7;
    int w  = hw & 127;

    unsigned long long acc[32];
#pragma unroll
    for (int j = 0; j < 32; j++) acc[j] = pack2(bsm[2 * j], bsm[2 * j + 1]);

    const float* xb = x + (b * CIN) * HW + hw;
    bool hm = h > 0, hp = h < 127, wm = w > 0, wp = w < 127;

#pragma unroll 1
    for (int ci = 0; ci < CIN; ci++) {
        const float* xc = xb + ci * HW;
        float t[9];
        t[0] = (hm && wm) ? xc[-129] : 0.f;
        t[1] =  hm        ? xc[-128] : 0.f;
        t[2] = (hm && wp) ? xc[-127] : 0.f;
        t[3] =  wm        ? xc[-1]   : 0.f;
        t[4] =              xc[0];
        t[5] =  wp        ? xc[1]    : 0.f;
        t[6] = (hp && wm) ? xc[127]  : 0.f;
        t[7] =  hp        ? xc[128]  : 0.f;
        t[8] = (hp && wp) ? xc[129]  : 0.f;
#pragma unroll
        for (int k = 0; k < 9; k++) {
            unsigned long long xx = pack2(t[k], t[k]);
            const ulonglong2* wr = (const ulonglong2*)&wsm[(ci * 9 + k) * 64];
#pragma unroll
            for (int j = 0; j < 16; j++) {
                ulonglong2 wv = wr[j];          // LDS.128, uniform -> broadcast
                fma2(acc[2 * j],     xx, wv.x);
                fma2(acc[2 * j + 1], xx, wv.y);
            }
        }
    }

    float* ob = out + (b * COUT) * HW + hw;
#pragma unroll
    for (int j = 0; j < 32; j++) {
        float lo = __uint_as_float((unsigned)(acc[j] & 0xFFFFFFFFull));
        float hi = __uint_as_float((unsigned)(acc[j] >> 32));
        atomicAdd(&ob[(2 * j)     * HW], gwt * lo);   // RED, exactly 2 adds/elem (commutative -> deterministic)
        atomicAdd(&ob[(2 * j + 1) * HW], gwt * hi);
    }
}

// ---------------- launch ----------------
extern "C" void kernel_launch(void* const* d_in, const int* in_sizes, int n_in,
                              void* d_out, int out_size) {
    const float* x  = (const float*)d_in[0];   // (8,16,128,128)
    const float* gw = (const float*)d_in[1];   // (16,16,1,1)
    const float* gb = (const float*)d_in[2];   // (16,)
    const float* ew = (const float*)d_in[3];   // (16,64,16,3,3)
    const float* eb = (const float*)d_in[4];   // (16,64)
    float* out    = (float*)d_out;             // out: 8,388,608 floats
    float* logits = out + LOGIT_OFF;           // logits: 2,097,152 floats

    reset_kernel<<<1, 32>>>();
    zero_out_kernel<<<8192, 256>>>((float4*)out);
    gate_kernel<<<512, 256>>>(x, gw, gb, logits);
    expert_kernel<<<dim3(512, 16), 256>>>(x, ew, eb, out);
    (void)in_sizes; (void)n_in; (void)out_size;
}